// round 14
// baseline (speedup 1.0000x reference)
#include <cuda_runtime.h>
#include <cstdint>
#include <cstddef>

#define TT 512
#define BB 16
#define EE 1024
#define HH 512
#define G3 1536
#define SENT 0x7FC00001u

// pre-gate scratch [d][t][col][b]
__device__ float g_preg[(size_t)2 * TT * G3 * BB];
// tf32-pre-rounded h staging [d][t][k][b]; sentinel-filled each launch
__device__ float g_hstage[(size_t)2 * TT * HH * BB];
// tf32-pre-rounded GEMM inputs (written once per launch by convert kernel)
__device__ float g_xtf[(size_t)BB * TT * EE];
__device__ float g_wtf[2][(size_t)G3 * EE];

static __device__ __forceinline__ uint32_t f2tf(float f) {
    uint32_t r; asm("cvt.rna.tf32.f32 %0, %1;" : "=r"(r) : "f"(f)); return r;
}
static __device__ __forceinline__ float f2tff(float f) { return __uint_as_float(f2tf(f)); }
static __device__ __forceinline__ float rcpa(float x) {
    float r; asm("rcp.approx.f32 %0, %1;" : "=f"(r) : "f"(x)); return r;
}

static __device__ __forceinline__ void mma8(float& d0, float& d1, float& d2, float& d3,
                                            uint32_t a0, uint32_t a1, uint32_t a2, uint32_t a3,
                                            uint32_t b0, uint32_t b1) {
    asm volatile(
        "mma.sync.aligned.m16n8k8.row.col.f32.tf32.tf32.f32 "
        "{%0,%1,%2,%3}, {%4,%5,%6,%7}, {%8,%9}, {%0,%1,%2,%3};"
        : "+f"(d0), "+f"(d1), "+f"(d2), "+f"(d3)
        : "r"(a0), "r"(a1), "r"(a2), "r"(a3), "r"(b0), "r"(b1));
}

// L1-bypassing (gpu-scope) loads/stores for the producer-consumer handoff
static __device__ __forceinline__ float4 ld_rlx4(const float* p) {
    float4 v;
    asm volatile("ld.relaxed.gpu.global.v4.f32 {%0,%1,%2,%3}, [%4];"
                 : "=f"(v.x), "=f"(v.y), "=f"(v.z), "=f"(v.w) : "l"(p) : "memory");
    return v;
}
static __device__ __forceinline__ void st_rlx(float* p, float v) {
    asm volatile("st.relaxed.gpu.global.f32 [%0], %1;" :: "l"(p), "f"(v) : "memory");
}
static __device__ __forceinline__ bool has_sent(float4 v) {
    return (__float_as_uint(v.x) == SENT) | (__float_as_uint(v.y) == SENT) |
           (__float_as_uint(v.z) == SENT) | (__float_as_uint(v.w) == SENT);
}

static __device__ __forceinline__ void cp_async16(uint32_t smem_addr, const void* gptr) {
    asm volatile("cp.async.ca.shared.global [%0], [%1], 16;"
                 :: "r"(smem_addr), "l"(gptr) : "memory");
}

// fill g_hstage with the sentinel pattern (runs first, every launch)
__global__ void fill_sentinel_kernel() {
    const size_t n4 = (size_t)2 * TT * HH * BB / 4;
    uint4 s = make_uint4(SENT, SENT, SENT, SENT);
    uint4* p = reinterpret_cast<uint4*>(g_hstage);
    for (size_t i = blockIdx.x * (size_t)blockDim.x + threadIdx.x; i < n4;
         i += (size_t)gridDim.x * blockDim.x)
        p[i] = s;
}

// pre-round x and the first EE columns of both W's to tf32 (once per launch)
__global__ void convert_tf32_kernel(const float* __restrict__ x,
                                    const float* __restrict__ wf,
                                    const float* __restrict__ wb) {
    const size_t stride = (size_t)gridDim.x * blockDim.x;
    const size_t base = blockIdx.x * (size_t)blockDim.x + threadIdx.x;
    const size_t nx4 = (size_t)BB * TT * EE / 4;
    for (size_t i = base; i < nx4; i += stride) {
        float4 v = reinterpret_cast<const float4*>(x)[i];
        reinterpret_cast<float4*>(g_xtf)[i] =
            make_float4(f2tff(v.x), f2tff(v.y), f2tff(v.z), f2tff(v.w));
    }
    const size_t nw4 = (size_t)G3 * EE / 4;
    for (size_t i = base; i < nw4; i += stride) {
        size_t r = i / (EE / 4), cq = i % (EE / 4);
        float4 vf = *reinterpret_cast<const float4*>(wf + r * G3 + cq * 4);
        float4 vb = *reinterpret_cast<const float4*>(wb + r * G3 + cq * 4);
        reinterpret_cast<float4*>(g_wtf[0])[i] =
            make_float4(f2tff(vf.x), f2tff(vf.y), f2tff(vf.z), f2tff(vf.w));
        reinterpret_cast<float4*>(g_wtf[1])[i] =
            make_float4(f2tff(vb.x), f2tff(vb.y), f2tff(vb.z), f2tff(vb.w));
    }
}

// ---------------------------------------------------------------------------
// Phase 1: pre-gates = x @ W_x^T + bias (tf32 mma GEMM, cp.async 2-stage).
// ---------------------------------------------------------------------------
#define PT (128 * 36)

__global__ __launch_bounds__(256) void pregemm_kernel(
    const float* __restrict__ bf, const float* __restrict__ bb) {
    extern __shared__ float psm[];
    const int d = blockIdx.z;
    const float* __restrict__ wtf  = g_wtf[d];
    const float* __restrict__ bias = d ? bb : bf;
    const int row0 = blockIdx.y * 128;
    const int col0 = blockIdx.x * 128;

    const int tid = threadIdx.x;
    const int lane = tid & 31, wid = tid >> 5;
    const int wm = wid >> 2, wn = wid & 3;
    const int g = lane >> 2, t4 = lane & 3;
    const int cm = tid >> 3;
    const int ckq = (tid & 7) * 4;

    float acc[4][4][4];
#pragma unroll
    for (int i = 0; i < 4; i++)
#pragma unroll
        for (int j = 0; j < 4; j++)
#pragma unroll
            for (int r = 0; r < 4; r++) acc[i][j][r] = 0.f;

    auto issue_stage = [&](int st, int k0) {
        float* As = psm + st * 2 * PT;
        float* Bs = As + PT;
#pragma unroll
        for (int i = 0; i < 4; i++) {
            int m = cm + i * 32;
            int row = row0 + m;
            int t = row >> 4, b = row & 15;
            cp_async16((uint32_t)__cvta_generic_to_shared(&As[m * 36 + ckq]),
                       g_xtf + (size_t)(b * TT + t) * EE + k0 + ckq);
            cp_async16((uint32_t)__cvta_generic_to_shared(&Bs[m * 36 + ckq]),
                       wtf + (size_t)(col0 + m) * EE + k0 + ckq);
        }
        asm volatile("cp.async.commit_group;" ::: "memory");
    };

    issue_stage(0, 0);

    for (int kb = 0; kb < 32; kb++) {
        asm volatile("cp.async.wait_group 0;" ::: "memory");
        __syncthreads();
        if (kb < 31) issue_stage((kb + 1) & 1, (kb + 1) * 32);

        const float* As = psm + (kb & 1) * 2 * PT;
        const float* Bs = As + PT;
#pragma unroll
        for (int kt = 0; kt < 4; kt++) {
            int k = kt * 8;
            uint32_t a[4][4];
#pragma unroll
            for (int mt = 0; mt < 4; mt++) {
                int mb = wm * 64 + mt * 16;
                a[mt][0] = __float_as_uint(As[(mb + g) * 36 + k + t4]);
                a[mt][1] = __float_as_uint(As[(mb + g + 8) * 36 + k + t4]);
                a[mt][2] = __float_as_uint(As[(mb + g) * 36 + k + 4 + t4]);
                a[mt][3] = __float_as_uint(As[(mb + g + 8) * 36 + k + 4 + t4]);
            }
#pragma unroll
            for (int nt = 0; nt < 4; nt++) {
                int nb = wn * 32 + nt * 8;
                uint32_t b0 = __float_as_uint(Bs[(nb + g) * 36 + k + t4]);
                uint32_t b1 = __float_as_uint(Bs[(nb + g) * 36 + k + 4 + t4]);
#pragma unroll
                for (int mt = 0; mt < 4; mt++)
                    mma8(acc[mt][nt][0], acc[mt][nt][1], acc[mt][nt][2], acc[mt][nt][3],
                         a[mt][0], a[mt][1], a[mt][2], a[mt][3], b0, b1);
            }
        }
    }

#pragma unroll
    for (int mt = 0; mt < 4; mt++) {
        int rowb = row0 + wm * 64 + mt * 16 + g;
#pragma unroll
        for (int nt = 0; nt < 4; nt++) {
            int colb = col0 + wn * 32 + nt * 8 + 2 * t4;
#pragma unroll
            for (int r = 0; r < 4; r++) {
                int row = rowb + ((r >= 2) ? 8 : 0);
                int col = colb + (r & 1);
                int t = row >> 4, b = row & 15;
                float v = acc[mt][nt][r] + __ldg(bias + col);
                g_preg[(((size_t)d * TT + t) * G3 + col) * BB + b] = v;
            }
        }
    }
}

// ---------------------------------------------------------------------------
// Phase 2: persistent recurrence — 32 CTAs/dir (16 h-cols each): halves the
// producer population (straggler max over 32, not 64), halves handoff read
// traffic and poll pressure. All R10/R13 mechanics preserved: warp-owned
// 128B hst lines, publish-first, cheap 16B detect spin + one-shot verify,
// parity reduce, one CTA barrier/step, deferred coalesced out.
// ---------------------------------------------------------------------------
#define WPAD 516
#define RPAD 49

__global__ __launch_bounds__(256) void recur_kernel(
    const float* __restrict__ wf, const float* __restrict__ wb,
    const float* __restrict__ h0f, const float* __restrict__ h0b,
    const float* __restrict__ c0f, const float* __restrict__ c0b,
    float* __restrict__ out) {
    extern __shared__ float sm[];
    float* hsm = sm;                       // 16 x WPAD  (h_{t-1} [b][k])
    float* red = sm + 16 * WPAD;           // 2 x 8 x 16 x RPAD (parity)
    float* hT  = red + 2 * 8 * 16 * RPAD;  // 2 x 320 parity h buffer

    const int d   = (int)blockIdx.x >> 5;
    const int grp = (int)blockIdx.x & 31;
    const int n0  = grp * 16;
    const float* __restrict__ w  = d ? wb : wf;
    const float* __restrict__ h0 = d ? h0b : h0f;
    const float* __restrict__ c0 = d ? c0b : c0f;
    const float* __restrict__ preg = g_preg + (size_t)d * TT * G3 * BB;
    float* __restrict__ hst = g_hstage + (size_t)d * TT * HH * BB;

    const int tid = threadIdx.x, lane = tid & 31, wid = tid >> 5;
    const int g = lane >> 2, t4 = lane & 3;
    // epilogue mapping: warp w owns cols 2w,2w+1 x all 16 batches (128B line)
    const int eb = tid & 15, en = tid >> 4;          // en 0..15
    // out-writeback mapping (coalesced 64B runs)
    const int en2 = tid & 15, eb2 = tid >> 4;
    const int kbase = wid * 64;       // this warp's K slice
    const int k2 = tid * 2;           // the 2 k-columns I stage (one 128B line)

    // Preload this thread's W_h B-fragments into registers (tf32).
    // nt = gi*2+cg: gate gi (i/j/o), column-half cg (cols n0+8cg..n0+8cg+7)
    float breg[8][6][2];
#pragma unroll
    for (int gi = 0; gi < 3; gi++)
#pragma unroll
        for (int cg = 0; cg < 2; cg++) {
            const int nt = gi * 2 + cg;
            const float* wr = w + (size_t)(gi * 512 + n0 + cg * 8 + g) * G3 + 1024;
#pragma unroll
            for (int kt = 0; kt < 8; kt++) {
                int col = kbase + kt * 8;
                breg[kt][nt][0] = f2tff(__ldg(wr + col + t4));
                breg[kt][nt][1] = f2tff(__ldg(wr + col + 4 + t4));
            }
        }
    float c = c0[n0 + en];  // cell state in a register (all 256 threads epi)

    // step-0 h: broadcast h0 over batch into my 2 columns
    {
        float2 o = make_float2(f2tff(h0[k2]), f2tff(h0[k2 + 1]));
#pragma unroll
        for (int b = 0; b < 16; b++)
            *reinterpret_cast<float2*>(&hsm[b * WPAD + k2]) = o;
    }
    __syncthreads();

    for (int s = 0; s < TT; s++) {
        const int tt = d ? (TT - 1 - s) : s;
        const int par = s & 1;
        float* redp = red + par * (8 * 16 * RPAD);

        // pre-gate prefetch (independent; overlaps the poll below)
        float pgi = __ldg(preg + ((size_t)tt * G3 + (n0 + en)) * BB + eb);
        float pgj = __ldg(preg + ((size_t)tt * G3 + (512 + n0 + en)) * BB + eb);
        float pgo = __ldg(preg + ((size_t)tt * G3 + (1024 + n0 + en)) * BB + eb);

        if (s > 0) {
            // poll MY line (data-as-flag): spin on first 16B, then verify all
            const int tp = d ? (tt + 1) : (tt - 1);
            const float* sp = hst + ((size_t)tp * HH + k2) * BB;
            float4 v[8];
            do { v[0] = ld_rlx4(sp); } while (has_sent(v[0]));
            for (;;) {
                bool bad = false;
#pragma unroll
                for (int q = 1; q < 8; q++) {
                    v[q] = ld_rlx4(sp + q * 4);
                    bad |= has_sent(v[q]);
                }
                if (!bad) break;
            }
            // transpose: v[0..3] = col k2 (b 0..15), v[4..7] = col k2+1
#pragma unroll
            for (int q = 0; q < 4; q++) {
                const float* a = &v[q].x;
                const float* bq = &v[4 + q].x;
#pragma unroll
                for (int r = 0; r < 4; r++)
                    *reinterpret_cast<float2*>(&hsm[(q * 4 + r) * WPAD + k2]) =
                        make_float2(a[r], bq[r]);
            }
        }
        __syncwarp();  // my warp's staging visible to my warp's mma

        // per-warp mma on its own K slice: A from SMEM, B from registers
        float acc[6][4];
#pragma unroll
        for (int nt = 0; nt < 6; nt++)
#pragma unroll
            for (int r = 0; r < 4; r++) acc[nt][r] = 0.f;

#pragma unroll
        for (int kt = 0; kt < 8; kt++) {
            int k = kbase + kt * 8;
            uint32_t a0 = __float_as_uint(hsm[g * WPAD + k + t4]);
            uint32_t a1 = __float_as_uint(hsm[(g + 8) * WPAD + k + t4]);
            uint32_t a2 = __float_as_uint(hsm[g * WPAD + k + 4 + t4]);
            uint32_t a3 = __float_as_uint(hsm[(g + 8) * WPAD + k + 4 + t4]);
#pragma unroll
            for (int nt = 0; nt < 6; nt++)
                mma8(acc[nt][0], acc[nt][1], acc[nt][2], acc[nt][3],
                     a0, a1, a2, a3,
                     __float_as_uint(breg[kt][nt][0]),
                     __float_as_uint(breg[kt][nt][1]));
        }

        // cross-warp K reduction via SMEM (parity-buffered)
        // nval layout: gate gi occupies [gi*16, gi*16+16)
        float* rw = redp + wid * 16 * RPAD;
#pragma unroll
        for (int nt = 0; nt < 6; nt++) {
            int gi = nt >> 1, cg = nt & 1;
            int rl = gi * 16 + cg * 8 + 2 * t4;
            rw[g * RPAD + rl]           = acc[nt][0];
            rw[g * RPAD + rl + 1]       = acc[nt][1];
            rw[(g + 8) * RPAD + rl]     = acc[nt][2];
            rw[(g + 8) * RPAD + rl + 1] = acc[nt][3];
        }
        __syncthreads();  // the single CTA-wide barrier per step

        {
            float si = pgi, sj = pgj, so = pgo;
#pragma unroll
            for (int wq = 0; wq < 8; wq++) {
                const float* rr = redp + (wq * 16 + eb) * RPAD;
                si += rr[en];
                sj += rr[16 + en];
                so += rr[32 + en];
            }
            // fast MUFU-only gates (err ~1e-6)
            float ig = rcpa(1.f + __expf(-si));
            float tj = 1.f - 2.f * rcpa(1.f + __expf(2.f * sj));
            c = (1.f - ig) * c + ig * tj;                       // coupled gate
            float tc = 1.f - 2.f * rcpa(1.f + __expf(2.f * c));
            float h = tc * rcpa(1.f + __expf(-so));

            // publish FIRST: my warp owns one full 128B hst line -> one
            // coalesced wavefront, atomic-ish arrival at L2
            st_rlx(hst + ((size_t)tt * HH + n0 + en) * BB + eb, f2tff(h));
            // stash full-precision h for the deferred out write
            hT[par * 320 + en * 20 + eb] = h;

            // deferred coalesced out write for step s-1 (off critical path)
            if (s > 0) {
                const float* hTp = hT + (par ^ 1) * 320;
                const int tprev = d ? (TT - s) : (s - 1);
                out[(size_t)(eb2 * TT + tprev) * 1024 + d * 512 + n0 + en2] =
                    hTp[en2 * 20 + eb2];
            }
        }
    }

    // flush the final step's out values
    __syncthreads();
    {
        const float* hTp = hT + ((TT - 1) & 1) * 320;
        const int tlast = d ? 0 : (TT - 1);
        out[(size_t)(eb2 * TT + tlast) * 1024 + d * 512 + n0 + en2] =
            hTp[en2 * 20 + eb2];
    }
}

extern "C" void kernel_launch(void* const* d_in, const int* in_sizes, int n_in,
                              void* d_out, int out_size) {
    (void)in_sizes; (void)n_in; (void)out_size;
    const float* x   = (const float*)d_in[0];
    const float* wf  = (const float*)d_in[1];
    const float* bf  = (const float*)d_in[2];
    const float* wb  = (const float*)d_in[3];
    const float* bb  = (const float*)d_in[4];
    const float* h0f = (const float*)d_in[5];
    const float* h0b = (const float*)d_in[6];
    const float* c0f = (const float*)d_in[7];
    const float* c0b = (const float*)d_in[8];
    float* out = (float*)d_out;

    const int psm_bytes = 4 * PT * 4;  // 73728
    cudaFuncSetAttribute(pregemm_kernel, cudaFuncAttributeMaxDynamicSharedMemorySize,
                         psm_bytes);
    const int rsm_bytes = (16 * WPAD + 2 * 8 * 16 * RPAD + 2 * 320) * 4;  // 85760
    cudaFuncSetAttribute(recur_kernel, cudaFuncAttributeMaxDynamicSharedMemorySize,
                         rsm_bytes);

    fill_sentinel_kernel<<<512, 256>>>();
    convert_tf32_kernel<<<512, 256>>>(x, wf, wb);
    dim3 g1(G3 / 128, (TT * BB) / 128, 2);
    pregemm_kernel<<<g1, 256, psm_bytes>>>(bf, bb);
    recur_kernel<<<64, 256, rsm_bytes>>>(wf, wb, h0f, h0b, c0f, c0b, out);
}

// round 15
// speedup vs baseline: 1.5199x; 1.5199x over previous
#include <cuda_runtime.h>
#include <cuda_fp16.h>
#include <cstdint>
#include <cstddef>

#define TT 512
#define BB 16
#define EE 1024
#define HH 512
#define G3 1536
#define SENTH 0x7C01u
#define SENTW 0x7C017C01u

// pre-gate scratch [d][t][col][b] (fp32)
__device__ float g_preg[(size_t)2 * TT * G3 * BB];
// fp16 h staging [d][t][k][b]; sentinel-filled each launch (16.8 MB)
__device__ unsigned short g_hst16[(size_t)2 * TT * HH * BB];
// tf32-pre-rounded GEMM inputs (written once per launch by convert kernel)
__device__ float g_xtf[(size_t)BB * TT * EE];
__device__ float g_wtf[2][(size_t)G3 * EE];

static __device__ __forceinline__ uint32_t f2tf(float f) {
    uint32_t r; asm("cvt.rna.tf32.f32 %0, %1;" : "=r"(r) : "f"(f)); return r;
}
static __device__ __forceinline__ float f2tff(float f) { return __uint_as_float(f2tf(f)); }
static __device__ __forceinline__ float rcpa(float x) {
    float r; asm("rcp.approx.f32 %0, %1;" : "=f"(r) : "f"(x)); return r;
}
static __device__ __forceinline__ uint32_t packh2(float a, float b) {
    __half2 h = __floats2half2_rn(a, b);
    return *reinterpret_cast<uint32_t*>(&h);
}

// tf32 mma (pregemm)
static __device__ __forceinline__ void mma8(float& d0, float& d1, float& d2, float& d3,
                                            uint32_t a0, uint32_t a1, uint32_t a2, uint32_t a3,
                                            uint32_t b0, uint32_t b1) {
    asm volatile(
        "mma.sync.aligned.m16n8k8.row.col.f32.tf32.tf32.f32 "
        "{%0,%1,%2,%3}, {%4,%5,%6,%7}, {%8,%9}, {%0,%1,%2,%3};"
        : "+f"(d0), "+f"(d1), "+f"(d2), "+f"(d3)
        : "r"(a0), "r"(a1), "r"(a2), "r"(a3), "r"(b0), "r"(b1));
}
// fp16 mma (recurrence), K=16
static __device__ __forceinline__ void mma16h(float& d0, float& d1, float& d2, float& d3,
                                              uint32_t a0, uint32_t a1, uint32_t a2, uint32_t a3,
                                              uint32_t b0, uint32_t b1) {
    asm volatile(
        "mma.sync.aligned.m16n8k16.row.col.f32.f16.f16.f32 "
        "{%0,%1,%2,%3}, {%4,%5,%6,%7}, {%8,%9}, {%0,%1,%2,%3};"
        : "+f"(d0), "+f"(d1), "+f"(d2), "+f"(d3)
        : "r"(a0), "r"(a1), "r"(a2), "r"(a3), "r"(b0), "r"(b1));
}

// L1-bypassing (gpu-scope) accesses for the handoff
static __device__ __forceinline__ uint4 ld_rlx4u(const void* p) {
    uint4 v;
    asm volatile("ld.relaxed.gpu.global.v4.u32 {%0,%1,%2,%3}, [%4];"
                 : "=r"(v.x), "=r"(v.y), "=r"(v.z), "=r"(v.w) : "l"(p) : "memory");
    return v;
}
static __device__ __forceinline__ void st_rlx16(unsigned short* p, unsigned short v) {
    asm volatile("st.relaxed.gpu.global.u16 [%0], %1;" :: "l"(p), "h"(v) : "memory");
}
static __device__ __forceinline__ bool wsent(uint32_t u) {
    return ((u & 0xFFFFu) == SENTH) | ((u >> 16) == SENTH);
}
static __device__ __forceinline__ bool hass(uint4 v) {
    return wsent(v.x) | wsent(v.y) | wsent(v.z) | wsent(v.w);
}

// fill g_hst16 with the fp16-NaN sentinel pattern (every launch)
__global__ void fill_sentinel_kernel() {
    const size_t n4 = (size_t)2 * TT * HH * BB / 8;  // uint4 count
    uint4 s = make_uint4(SENTW, SENTW, SENTW, SENTW);
    uint4* p = reinterpret_cast<uint4*>(g_hst16);
    for (size_t i = blockIdx.x * (size_t)blockDim.x + threadIdx.x; i < n4;
         i += (size_t)gridDim.x * blockDim.x)
        p[i] = s;
}

// pre-round x and the first EE columns of both W's to tf32 (once per launch)
__global__ void convert_tf32_kernel(const float* __restrict__ x,
                                    const float* __restrict__ wf,
                                    const float* __restrict__ wb) {
    const size_t stride = (size_t)gridDim.x * blockDim.x;
    const size_t base = blockIdx.x * (size_t)blockDim.x + threadIdx.x;
    const size_t nx4 = (size_t)BB * TT * EE / 4;
    for (size_t i = base; i < nx4; i += stride) {
        float4 v = reinterpret_cast<const float4*>(x)[i];
        reinterpret_cast<float4*>(g_xtf)[i] =
            make_float4(f2tff(v.x), f2tff(v.y), f2tff(v.z), f2tff(v.w));
    }
    const size_t nw4 = (size_t)G3 * EE / 4;
    for (size_t i = base; i < nw4; i += stride) {
        size_t r = i / (EE / 4), cq = i % (EE / 4);
        float4 vf = *reinterpret_cast<const float4*>(wf + r * G3 + cq * 4);
        float4 vb = *reinterpret_cast<const float4*>(wb + r * G3 + cq * 4);
        reinterpret_cast<float4*>(g_wtf[0])[i] =
            make_float4(f2tff(vf.x), f2tff(vf.y), f2tff(vf.z), f2tff(vf.w));
        reinterpret_cast<float4*>(g_wtf[1])[i] =
            make_float4(f2tff(vb.x), f2tff(vb.y), f2tff(vb.z), f2tff(vb.w));
    }
}

// ---------------------------------------------------------------------------
// Phase 1: pre-gates = x @ W_x^T + bias (tf32 mma GEMM, cp.async 2-stage).
// (unchanged from R13)
// ---------------------------------------------------------------------------
#define PT (128 * 36)

static __device__ __forceinline__ void cp_async16(uint32_t smem_addr, const void* gptr) {
    asm volatile("cp.async.ca.shared.global [%0], [%1], 16;"
                 :: "r"(smem_addr), "l"(gptr) : "memory");
}

__global__ __launch_bounds__(256) void pregemm_kernel(
    const float* __restrict__ bf, const float* __restrict__ bb) {
    extern __shared__ float psm[];
    const int d = blockIdx.z;
    const float* __restrict__ wtf  = g_wtf[d];
    const float* __restrict__ bias = d ? bb : bf;
    const int row0 = blockIdx.y * 128;
    const int col0 = blockIdx.x * 128;

    const int tid = threadIdx.x;
    const int lane = tid & 31, wid = tid >> 5;
    const int wm = wid >> 2, wn = wid & 3;
    const int g = lane >> 2, t4 = lane & 3;
    const int cm = tid >> 3;
    const int ckq = (tid & 7) * 4;

    float acc[4][4][4];
#pragma unroll
    for (int i = 0; i < 4; i++)
#pragma unroll
        for (int j = 0; j < 4; j++)
#pragma unroll
            for (int r = 0; r < 4; r++) acc[i][j][r] = 0.f;

    auto issue_stage = [&](int st, int k0) {
        float* As = psm + st * 2 * PT;
        float* Bs = As + PT;
#pragma unroll
        for (int i = 0; i < 4; i++) {
            int m = cm + i * 32;
            int row = row0 + m;
            int t = row >> 4, b = row & 15;
            cp_async16((uint32_t)__cvta_generic_to_shared(&As[m * 36 + ckq]),
                       g_xtf + (size_t)(b * TT + t) * EE + k0 + ckq);
            cp_async16((uint32_t)__cvta_generic_to_shared(&Bs[m * 36 + ckq]),
                       wtf + (size_t)(col0 + m) * EE + k0 + ckq);
        }
        asm volatile("cp.async.commit_group;" ::: "memory");
    };

    issue_stage(0, 0);

    for (int kb = 0; kb < 32; kb++) {
        asm volatile("cp.async.wait_group 0;" ::: "memory");
        __syncthreads();
        if (kb < 31) issue_stage((kb + 1) & 1, (kb + 1) * 32);

        const float* As = psm + (kb & 1) * 2 * PT;
        const float* Bs = As + PT;
#pragma unroll
        for (int kt = 0; kt < 4; kt++) {
            int k = kt * 8;
            uint32_t a[4][4];
#pragma unroll
            for (int mt = 0; mt < 4; mt++) {
                int mb = wm * 64 + mt * 16;
                a[mt][0] = __float_as_uint(As[(mb + g) * 36 + k + t4]);
                a[mt][1] = __float_as_uint(As[(mb + g + 8) * 36 + k + t4]);
                a[mt][2] = __float_as_uint(As[(mb + g) * 36 + k + 4 + t4]);
                a[mt][3] = __float_as_uint(As[(mb + g + 8) * 36 + k + 4 + t4]);
            }
#pragma unroll
            for (int nt = 0; nt < 4; nt++) {
                int nb = wn * 32 + nt * 8;
                uint32_t b0 = __float_as_uint(Bs[(nb + g) * 36 + k + t4]);
                uint32_t b1 = __float_as_uint(Bs[(nb + g) * 36 + k + 4 + t4]);
#pragma unroll
                for (int mt = 0; mt < 4; mt++)
                    mma8(acc[mt][nt][0], acc[mt][nt][1], acc[mt][nt][2], acc[mt][nt][3],
                         a[mt][0], a[mt][1], a[mt][2], a[mt][3], b0, b1);
            }
        }
    }

#pragma unroll
    for (int mt = 0; mt < 4; mt++) {
        int rowb = row0 + wm * 64 + mt * 16 + g;
#pragma unroll
        for (int nt = 0; nt < 4; nt++) {
            int colb = col0 + wn * 32 + nt * 8 + 2 * t4;
#pragma unroll
            for (int r = 0; r < 4; r++) {
                int row = rowb + ((r >= 2) ? 8 : 0);
                int col = colb + (r & 1);
                int t = row >> 4, b = row & 15;
                float v = acc[mt][nt][r] + __ldg(bias + col);
                g_preg[(((size_t)d * TT + t) * G3 + col) * BB + b] = v;
            }
        }
    }
}

// ---------------------------------------------------------------------------
// Phase 2: persistent recurrence — R13 topology (64 CTAs/dir, 8 cols each,
// 256 thr) with the handoff and recurrent mma moved to FP16 (same 11-bit
// precision as tf32 for |h|<=1). Halves handoff traffic, mma count, staging
// work. All confirmed mechanics kept: 16B detect spin + one-shot verify,
// publish-first, parity reduce, one CTA barrier/step, deferred out.
// ---------------------------------------------------------------------------
#define HPADW 260   // hsm row stride in 32-bit words (520 halves)
#define RPAD 25

__global__ __launch_bounds__(256) void recur_kernel(
    const float* __restrict__ wf, const float* __restrict__ wb,
    const float* __restrict__ h0f, const float* __restrict__ h0b,
    const float* __restrict__ c0f, const float* __restrict__ c0b,
    float* __restrict__ out) {
    extern __shared__ float sm[];
    uint32_t* hsm = reinterpret_cast<uint32_t*>(sm);  // 16 x HPADW words (h fp16x2)
    float* red = sm + 16 * HPADW;                     // 2 x 8 x 16 x RPAD (parity)
    float* hT  = red + 2 * 8 * 16 * RPAD;             // 2 x 160 parity h buffer

    const int d   = (int)blockIdx.x >> 6;
    const int grp = (int)blockIdx.x & 63;
    const int n0  = grp * 8;
    const float* __restrict__ w  = d ? wb : wf;
    const float* __restrict__ h0 = d ? h0b : h0f;
    const float* __restrict__ c0 = d ? c0b : c0f;
    const float* __restrict__ preg = g_preg + (size_t)d * TT * G3 * BB;
    unsigned short* __restrict__ hst = g_hst16 + (size_t)d * TT * HH * BB;

    const int tid = threadIdx.x, lane = tid & 31, wid = tid >> 5;
    const int g = lane >> 2, t4 = lane & 3;
    // epilogue mapping: warp w owns cols 2w,2w+1 x all 16 batches
    const int eb = tid & 15, en = (tid >> 4) & 7;
    // out-writeback mapping (coalesced)
    const int en2 = tid & 7, eb2 = (tid >> 3) & 15;
    const bool epi = tid < 128;
    const int kbase = wid * 64;       // this warp's K slice
    const int k2 = tid * 2;           // the 2 k-columns I stage (one 64B line)

    // Preload W_h B-fragments as packed fp16 pairs (24 regs).
    uint32_t breg[4][3][2];
#pragma unroll
    for (int gi = 0; gi < 3; gi++) {
        const float* wr = w + (size_t)(gi * 512 + n0 + g) * G3 + 1024;
#pragma unroll
        for (int kt = 0; kt < 4; kt++) {
            int kk = kbase + kt * 16 + 2 * t4;
            breg[kt][gi][0] = packh2(__ldg(wr + kk), __ldg(wr + kk + 1));
            breg[kt][gi][1] = packh2(__ldg(wr + kk + 8), __ldg(wr + kk + 9));
        }
    }
    float c = epi ? c0[n0 + en] : 0.f;  // cell state in a register

    // step-0 h: broadcast h0 over batch into my 2 columns (fp16 pair)
    {
        uint32_t o = packh2(h0[k2], h0[k2 + 1]);
#pragma unroll
        for (int b = 0; b < 16; b++) hsm[b * HPADW + tid] = o;
    }
    __syncthreads();

    for (int s = 0; s < TT; s++) {
        const int tt = d ? (TT - 1 - s) : s;
        const int par = s & 1;
        float* redp = red + par * (8 * 16 * RPAD);

        // pre-gate prefetch (independent; overlaps the poll below)
        float pgi = 0.f, pgj = 0.f, pgo = 0.f;
        if (epi) {
            pgi = __ldg(preg + ((size_t)tt * G3 + (n0 + en)) * BB + eb);
            pgj = __ldg(preg + ((size_t)tt * G3 + (512 + n0 + en)) * BB + eb);
            pgo = __ldg(preg + ((size_t)tt * G3 + (1024 + n0 + en)) * BB + eb);
        }

        if (s > 0) {
            // poll MY 64B line: 16B detect spin, then one-shot 48B verify
            const int tp = d ? (tt + 1) : (tt - 1);
            const unsigned short* sp = hst + ((size_t)tp * HH + k2) * BB;
            uint4 v0, v1, v2, v3;
            do { v0 = ld_rlx4u(sp); } while (hass(v0));
            for (;;) {
                v1 = ld_rlx4u(sp + 8);
                v2 = ld_rlx4u(sp + 16);
                v3 = ld_rlx4u(sp + 24);
                if (!(hass(v1) | hass(v2) | hass(v3))) break;
            }
            // v0:col k2 b0..7, v1:col k2 b8..15, v2:col k2+1 b0..7, v3:b8..15
            const uint32_t* lo0 = &v0.x;
            const uint32_t* lo1 = &v1.x;
            const uint32_t* hi0 = &v2.x;
            const uint32_t* hi1 = &v3.x;
#pragma unroll
            for (int b = 0; b < 16; b++) {
                uint32_t ul = (b < 8) ? lo0[b >> 1] : lo1[(b - 8) >> 1];
                uint32_t uh = (b < 8) ? hi0[b >> 1] : hi1[(b - 8) >> 1];
                uint32_t o = (b & 1) ? __byte_perm(ul, uh, 0x7632)
                                     : __byte_perm(ul, uh, 0x5410);
                hsm[b * HPADW + tid] = o;
            }
        }
        __syncwarp();  // my warp's staging visible to my warp's mma

        // per-warp fp16 mma on its own K slice (K=64 -> 4 k16-steps x 3 gates)
        float acc[3][4];
#pragma unroll
        for (int nt = 0; nt < 3; nt++)
#pragma unroll
            for (int r = 0; r < 4; r++) acc[nt][r] = 0.f;

#pragma unroll
        for (int kt = 0; kt < 4; kt++) {
            int kw = (kbase >> 1) + kt * 8;  // word offset into hsm row
            uint32_t a0 = hsm[g * HPADW + kw + t4];
            uint32_t a1 = hsm[(g + 8) * HPADW + kw + t4];
            uint32_t a2 = hsm[g * HPADW + kw + 4 + t4];
            uint32_t a3 = hsm[(g + 8) * HPADW + kw + 4 + t4];
#pragma unroll
            for (int nt = 0; nt < 3; nt++)
                mma16h(acc[nt][0], acc[nt][1], acc[nt][2], acc[nt][3],
                       a0, a1, a2, a3, breg[kt][nt][0], breg[kt][nt][1]);
        }

        // cross-warp K reduction via SMEM (parity-buffered)
        float* rw = redp + wid * 16 * RPAD;
#pragma unroll
        for (int nt = 0; nt < 3; nt++) {
            int rl = nt * 8 + 2 * t4;
            rw[g * RPAD + rl]           = acc[nt][0];
            rw[g * RPAD + rl + 1]       = acc[nt][1];
            rw[(g + 8) * RPAD + rl]     = acc[nt][2];
            rw[(g + 8) * RPAD + rl + 1] = acc[nt][3];
        }
        __syncthreads();  // the single CTA-wide barrier per step

        if (epi) {
            float si = pgi, sj = pgj, so = pgo;
#pragma unroll
            for (int wq = 0; wq < 8; wq++) {
                const float* rr = redp + (wq * 16 + eb) * RPAD;
                si += rr[en];
                sj += rr[8 + en];
                so += rr[16 + en];
            }
            // fast MUFU-only gates (err ~1e-6)
            float ig = rcpa(1.f + __expf(-si));
            float tj = 1.f - 2.f * rcpa(1.f + __expf(2.f * sj));
            c = (1.f - ig) * c + ig * tj;                       // coupled gate
            float tc = 1.f - 2.f * rcpa(1.f + __expf(2.f * c));
            float h = tc * rcpa(1.f + __expf(-so));

            // publish FIRST: fp16 h, warp-owned 64B line, one wavefront
            unsigned short hv = __half_as_ushort(__float2half_rn(h));
            st_rlx16(hst + ((size_t)tt * HH + n0 + en) * BB + eb, hv);
            // stash full-precision h for the deferred out write
            hT[par * 160 + en * 20 + eb] = h;

            // deferred coalesced out write for step s-1 (off critical path)
            if (s > 0) {
                const float* hTp = hT + (par ^ 1) * 160;
                const int tprev = d ? (TT - s) : (s - 1);
                out[(size_t)(eb2 * TT + tprev) * 1024 + d * 512 + n0 + en2] =
                    hTp[en2 * 20 + eb2];
            }
        }
    }

    // flush the final step's out values
    __syncthreads();
    if (epi) {
        const float* hTp = hT + ((TT - 1) & 1) * 160;
        const int tlast = d ? 0 : (TT - 1);
        out[(size_t)(eb2 * TT + tlast) * 1024 + d * 512 + n0 + en2] =
            hTp[en2 * 20 + eb2];
    }
}

extern "C" void kernel_launch(void* const* d_in, const int* in_sizes, int n_in,
                              void* d_out, int out_size) {
    (void)in_sizes; (void)n_in; (void)out_size;
    const float* x   = (const float*)d_in[0];
    const float* wf  = (const float*)d_in[1];
    const float* bf  = (const float*)d_in[2];
    const float* wb  = (const float*)d_in[3];
    const float* bb  = (const float*)d_in[4];
    const float* h0f = (const float*)d_in[5];
    const float* h0b = (const float*)d_in[6];
    const float* c0f = (const float*)d_in[7];
    const float* c0b = (const float*)d_in[8];
    float* out = (float*)d_out;

    const int psm_bytes = 4 * PT * 4;  // 73728
    cudaFuncSetAttribute(pregemm_kernel, cudaFuncAttributeMaxDynamicSharedMemorySize,
                         psm_bytes);
    const int rsm_bytes = (16 * HPADW + 2 * 8 * 16 * RPAD + 2 * 160) * 4;  // 43520
    cudaFuncSetAttribute(recur_kernel, cudaFuncAttributeMaxDynamicSharedMemorySize,
                         rsm_bytes);

    fill_sentinel_kernel<<<256, 256>>>();
    convert_tf32_kernel<<<512, 256>>>(x, wf, wb);
    dim3 g1(G3 / 128, (TT * BB) / 128, 2);
    pregemm_kernel<<<g1, 256, psm_bytes>>>(bf, bb);
    recur_kernel<<<128, 256, rsm_bytes>>>(wf, wb, h0f, h0b, c0f, c0b, out);
}

// round 16
// speedup vs baseline: 1.6261x; 1.0699x over previous
#include <cuda_runtime.h>
#include <cuda_fp16.h>
#include <cstdint>
#include <cstddef>

#define TT 512
#define BB 16
#define EE 1024
#define HH 512
#define G3 1536
#define SENTH 0x7C01u
#define SENTW 0x7C017C01u

// pre-gate scratch [d][t][col][b] (fp32)
__device__ float g_preg[(size_t)2 * TT * G3 * BB];
// fp16 h staging [d][t][k][b]; sentinel-filled each launch
__device__ unsigned short g_hst16[(size_t)2 * TT * HH * BB];
// fp16 GEMM inputs (written once per launch by convert kernel)
__device__ __half g_xh[(size_t)BB * TT * EE];
__device__ __half g_wh[2][(size_t)G3 * EE];

static __device__ __forceinline__ float rcpa(float x) {
    float r; asm("rcp.approx.f32 %0, %1;" : "=f"(r) : "f"(x)); return r;
}
static __device__ __forceinline__ uint32_t packh2(float a, float b) {
    __half2 h = __floats2half2_rn(a, b);
    return *reinterpret_cast<uint32_t*>(&h);
}

// fp16 mma, K=16, fp32 accumulate
static __device__ __forceinline__ void mma16h(float& d0, float& d1, float& d2, float& d3,
                                              uint32_t a0, uint32_t a1, uint32_t a2, uint32_t a3,
                                              uint32_t b0, uint32_t b1) {
    asm volatile(
        "mma.sync.aligned.m16n8k16.row.col.f32.f16.f16.f32 "
        "{%0,%1,%2,%3}, {%4,%5,%6,%7}, {%8,%9}, {%0,%1,%2,%3};"
        : "+f"(d0), "+f"(d1), "+f"(d2), "+f"(d3)
        : "r"(a0), "r"(a1), "r"(a2), "r"(a3), "r"(b0), "r"(b1));
}

// L1-bypassing (gpu-scope) accesses for the handoff
static __device__ __forceinline__ uint4 ld_rlx4u(const void* p) {
    uint4 v;
    asm volatile("ld.relaxed.gpu.global.v4.u32 {%0,%1,%2,%3}, [%4];"
                 : "=r"(v.x), "=r"(v.y), "=r"(v.z), "=r"(v.w) : "l"(p) : "memory");
    return v;
}
static __device__ __forceinline__ void st_rlx16(unsigned short* p, unsigned short v) {
    asm volatile("st.relaxed.gpu.global.u16 [%0], %1;" :: "l"(p), "h"(v) : "memory");
}
static __device__ __forceinline__ bool wsent(uint32_t u) {
    return ((u & 0xFFFFu) == SENTH) | ((u >> 16) == SENTH);
}
static __device__ __forceinline__ bool hass(uint4 v) {
    return wsent(v.x) | wsent(v.y) | wsent(v.z) | wsent(v.w);
}

// fill g_hst16 with the fp16-NaN sentinel pattern (every launch)
__global__ void fill_sentinel_kernel() {
    const size_t n4 = (size_t)2 * TT * HH * BB / 8;
    uint4 s = make_uint4(SENTW, SENTW, SENTW, SENTW);
    uint4* p = reinterpret_cast<uint4*>(g_hst16);
    for (size_t i = blockIdx.x * (size_t)blockDim.x + threadIdx.x; i < n4;
         i += (size_t)gridDim.x * blockDim.x)
        p[i] = s;
}

// convert x and the first EE columns of both W's to fp16 (once per launch)
__global__ void convert_fp16_kernel(const float* __restrict__ x,
                                    const float* __restrict__ wf,
                                    const float* __restrict__ wb) {
    const size_t stride = (size_t)gridDim.x * blockDim.x;
    const size_t base = blockIdx.x * (size_t)blockDim.x + threadIdx.x;
    const size_t nx4 = (size_t)BB * TT * EE / 4;
    for (size_t i = base; i < nx4; i += stride) {
        float4 v = reinterpret_cast<const float4*>(x)[i];
        reinterpret_cast<uint2*>(g_xh)[i] =
            make_uint2(packh2(v.x, v.y), packh2(v.z, v.w));
    }
    const size_t nw4 = (size_t)G3 * EE / 4;
    for (size_t i = base; i < nw4; i += stride) {
        size_t r = i / (EE / 4), cq = i % (EE / 4);
        float4 vf = *reinterpret_cast<const float4*>(wf + r * G3 + cq * 4);
        float4 vb = *reinterpret_cast<const float4*>(wb + r * G3 + cq * 4);
        reinterpret_cast<uint2*>(g_wh[0])[i] =
            make_uint2(packh2(vf.x, vf.y), packh2(vf.z, vf.w));
        reinterpret_cast<uint2*>(g_wh[1])[i] =
            make_uint2(packh2(vb.x, vb.y), packh2(vb.z, vb.w));
    }
}

// ---------------------------------------------------------------------------
// Phase 1: pre-gates = x @ W_x^T + bias — now FP16 mma (m16n8k16), fp32 acc.
// M = 8192, N = 1536, K = 1024. CTA tile 128x128x32 halves, 8 warps (2x4),
// warp tile 64x32. cp.async 2-stage pipeline; tile rows padded to 20 words
// (80B, 16B-aligned, conflict-free fragment loads: 20g+t4 distinct mod 32).
// ---------------------------------------------------------------------------
#define PTH (128 * 20)  // words per tile

static __device__ __forceinline__ void cp_async16(uint32_t smem_addr, const void* gptr) {
    asm volatile("cp.async.ca.shared.global [%0], [%1], 16;"
                 :: "r"(smem_addr), "l"(gptr) : "memory");
}

__global__ __launch_bounds__(256) void pregemm_kernel(
    const float* __restrict__ bf, const float* __restrict__ bb) {
    extern __shared__ uint32_t psm[];  // [2][ A(128*20) | B(128*20) ] words
    const int d = blockIdx.z;
    const __half* __restrict__ wh   = g_wh[d];
    const float* __restrict__ bias = d ? bb : bf;
    const int row0 = blockIdx.y * 128;
    const int col0 = blockIdx.x * 128;

    const int tid = threadIdx.x;
    const int lane = tid & 31, wid = tid >> 5;
    const int wm = wid >> 2, wn = wid & 3;
    const int g = lane >> 2, t4 = lane & 3;

    float acc[4][4][4];
#pragma unroll
    for (int i = 0; i < 4; i++)
#pragma unroll
        for (int j = 0; j < 4; j++)
#pragma unroll
            for (int r = 0; r < 4; r++) acc[i][j][r] = 0.f;

    // loader: 512 16B-chunks per tile; 2 chunks per thread per tile
    auto issue_stage = [&](int st, int k0) {
        uint32_t* As = psm + st * 2 * PTH;
        uint32_t* Bs = As + PTH;
#pragma unroll
        for (int i = 0; i < 2; i++) {
            int idx = tid + i * 256;
            int m = idx >> 2, ch = idx & 3;   // row, 16B-chunk within row
            int row = row0 + m;
            int t = row >> 4, b = row & 15;
            cp_async16((uint32_t)__cvta_generic_to_shared(&As[m * 20 + ch * 4]),
                       g_xh + (size_t)(b * TT + t) * EE + k0 + ch * 8);
            cp_async16((uint32_t)__cvta_generic_to_shared(&Bs[m * 20 + ch * 4]),
                       wh + (size_t)(col0 + m) * EE + k0 + ch * 8);
        }
        asm volatile("cp.async.commit_group;" ::: "memory");
    };

    issue_stage(0, 0);

    for (int kb = 0; kb < 32; kb++) {
        asm volatile("cp.async.wait_group 0;" ::: "memory");
        __syncthreads();
        if (kb < 31) issue_stage((kb + 1) & 1, (kb + 1) * 32);

        const uint32_t* As = psm + (kb & 1) * 2 * PTH;
        const uint32_t* Bs = As + PTH;
#pragma unroll
        for (int kt = 0; kt < 2; kt++) {
            int kw = kt * 8;  // word offset of this k16 group
            uint32_t a[4][4];
#pragma unroll
            for (int mt = 0; mt < 4; mt++) {
                int mb = wm * 64 + mt * 16;
                a[mt][0] = As[(mb + g) * 20 + kw + t4];
                a[mt][1] = As[(mb + g + 8) * 20 + kw + t4];
                a[mt][2] = As[(mb + g) * 20 + kw + 4 + t4];
                a[mt][3] = As[(mb + g + 8) * 20 + kw + 4 + t4];
            }
#pragma unroll
            for (int nt = 0; nt < 4; nt++) {
                int nb = wn * 32 + nt * 8;
                uint32_t b0 = Bs[(nb + g) * 20 + kw + t4];
                uint32_t b1 = Bs[(nb + g) * 20 + kw + 4 + t4];
#pragma unroll
                for (int mt = 0; mt < 4; mt++)
                    mma16h(acc[mt][nt][0], acc[mt][nt][1], acc[mt][nt][2], acc[mt][nt][3],
                           a[mt][0], a[mt][1], a[mt][2], a[mt][3], b0, b1);
            }
        }
    }

#pragma unroll
    for (int mt = 0; mt < 4; mt++) {
        int rowb = row0 + wm * 64 + mt * 16 + g;
#pragma unroll
        for (int nt = 0; nt < 4; nt++) {
            int colb = col0 + wn * 32 + nt * 8 + 2 * t4;
#pragma unroll
            for (int r = 0; r < 4; r++) {
                int row = rowb + ((r >= 2) ? 8 : 0);
                int col = colb + (r & 1);
                int t = row >> 4, b = row & 15;
                float v = acc[mt][nt][r] + __ldg(bias + col);
                g_preg[(((size_t)d * TT + t) * G3 + col) * BB + b] = v;
            }
        }
    }
}

// ---------------------------------------------------------------------------
// Phase 2: persistent recurrence — byte-exact R15 (best config, 912us):
// fp16 handoff + fp16 mma, warp-owned 64B hst lines, 16B detect spin +
// one-shot verify, publish-first, parity reduce, deferred coalesced out.
// ---------------------------------------------------------------------------
#define HPADW 260   // hsm row stride in 32-bit words
#define RPAD 25

__global__ __launch_bounds__(256) void recur_kernel(
    const float* __restrict__ wf, const float* __restrict__ wb,
    const float* __restrict__ h0f, const float* __restrict__ h0b,
    const float* __restrict__ c0f, const float* __restrict__ c0b,
    float* __restrict__ out) {
    extern __shared__ float sm[];
    uint32_t* hsm = reinterpret_cast<uint32_t*>(sm);  // 16 x HPADW words
    float* red = sm + 16 * HPADW;                     // 2 x 8 x 16 x RPAD
    float* hT  = red + 2 * 8 * 16 * RPAD;             // 2 x 160

    const int d   = (int)blockIdx.x >> 6;
    const int grp = (int)blockIdx.x & 63;
    const int n0  = grp * 8;
    const float* __restrict__ w  = d ? wb : wf;
    const float* __restrict__ h0 = d ? h0b : h0f;
    const float* __restrict__ c0 = d ? c0b : c0f;
    const float* __restrict__ preg = g_preg + (size_t)d * TT * G3 * BB;
    unsigned short* __restrict__ hst = g_hst16 + (size_t)d * TT * HH * BB;

    const int tid = threadIdx.x, lane = tid & 31, wid = tid >> 5;
    const int g = lane >> 2, t4 = lane & 3;
    const int eb = tid & 15, en = (tid >> 4) & 7;
    const int en2 = tid & 7, eb2 = (tid >> 3) & 15;
    const bool epi = tid < 128;
    const int kbase = wid * 64;
    const int k2 = tid * 2;

    uint32_t breg[4][3][2];
#pragma unroll
    for (int gi = 0; gi < 3; gi++) {
        const float* wr = w + (size_t)(gi * 512 + n0 + g) * G3 + 1024;
#pragma unroll
        for (int kt = 0; kt < 4; kt++) {
            int kk = kbase + kt * 16 + 2 * t4;
            breg[kt][gi][0] = packh2(__ldg(wr + kk), __ldg(wr + kk + 1));
            breg[kt][gi][1] = packh2(__ldg(wr + kk + 8), __ldg(wr + kk + 9));
        }
    }
    float c = epi ? c0[n0 + en] : 0.f;

    {
        uint32_t o = packh2(h0[k2], h0[k2 + 1]);
#pragma unroll
        for (int b = 0; b < 16; b++) hsm[b * HPADW + tid] = o;
    }
    __syncthreads();

    for (int s = 0; s < TT; s++) {
        const int tt = d ? (TT - 1 - s) : s;
        const int par = s & 1;
        float* redp = red + par * (8 * 16 * RPAD);

        float pgi = 0.f, pgj = 0.f, pgo = 0.f;
        if (epi) {
            pgi = __ldg(preg + ((size_t)tt * G3 + (n0 + en)) * BB + eb);
            pgj = __ldg(preg + ((size_t)tt * G3 + (512 + n0 + en)) * BB + eb);
            pgo = __ldg(preg + ((size_t)tt * G3 + (1024 + n0 + en)) * BB + eb);
        }

        if (s > 0) {
            const int tp = d ? (tt + 1) : (tt - 1);
            const unsigned short* sp = hst + ((size_t)tp * HH + k2) * BB;
            uint4 v0, v1, v2, v3;
            do { v0 = ld_rlx4u(sp); } while (hass(v0));
            for (;;) {
                v1 = ld_rlx4u(sp + 8);
                v2 = ld_rlx4u(sp + 16);
                v3 = ld_rlx4u(sp + 24);
                if (!(hass(v1) | hass(v2) | hass(v3))) break;
            }
            const uint32_t* lo0 = &v0.x;
            const uint32_t* lo1 = &v1.x;
            const uint32_t* hi0 = &v2.x;
            const uint32_t* hi1 = &v3.x;
#pragma unroll
            for (int b = 0; b < 16; b++) {
                uint32_t ul = (b < 8) ? lo0[b >> 1] : lo1[(b - 8) >> 1];
                uint32_t uh = (b < 8) ? hi0[b >> 1] : hi1[(b - 8) >> 1];
                uint32_t o = (b & 1) ? __byte_perm(ul, uh, 0x7632)
                                     : __byte_perm(ul, uh, 0x5410);
                hsm[b * HPADW + tid] = o;
            }
        }
        __syncwarp();

        float acc[3][4];
#pragma unroll
        for (int nt = 0; nt < 3; nt++)
#pragma unroll
            for (int r = 0; r < 4; r++) acc[nt][r] = 0.f;

#pragma unroll
        for (int kt = 0; kt < 4; kt++) {
            int kw = (kbase >> 1) + kt * 8;
            uint32_t a0 = hsm[g * HPADW + kw + t4];
            uint32_t a1 = hsm[(g + 8) * HPADW + kw + t4];
            uint32_t a2 = hsm[g * HPADW + kw + 4 + t4];
            uint32_t a3 = hsm[(g + 8) * HPADW + kw + 4 + t4];
#pragma unroll
            for (int nt = 0; nt < 3; nt++)
                mma16h(acc[nt][0], acc[nt][1], acc[nt][2], acc[nt][3],
                       a0, a1, a2, a3, breg[kt][nt][0], breg[kt][nt][1]);
        }

        float* rw = redp + wid * 16 * RPAD;
#pragma unroll
        for (int nt = 0; nt < 3; nt++) {
            int rl = nt * 8 + 2 * t4;
            rw[g * RPAD + rl]           = acc[nt][0];
            rw[g * RPAD + rl + 1]       = acc[nt][1];
            rw[(g + 8) * RPAD + rl]     = acc[nt][2];
            rw[(g + 8) * RPAD + rl + 1] = acc[nt][3];
        }
        __syncthreads();

        if (epi) {
            float si = pgi, sj = pgj, so = pgo;
#pragma unroll
            for (int wq = 0; wq < 8; wq++) {
                const float* rr = redp + (wq * 16 + eb) * RPAD;
                si += rr[en];
                sj += rr[8 + en];
                so += rr[16 + en];
            }
            float ig = rcpa(1.f + __expf(-si));
            float tj = 1.f - 2.f * rcpa(1.f + __expf(2.f * sj));
            c = (1.f - ig) * c + ig * tj;
            float tc = 1.f - 2.f * rcpa(1.f + __expf(2.f * c));
            float h = tc * rcpa(1.f + __expf(-so));

            unsigned short hv = __half_as_ushort(__float2half_rn(h));
            st_rlx16(hst + ((size_t)tt * HH + n0 + en) * BB + eb, hv);
            hT[par * 160 + en * 20 + eb] = h;

            if (s > 0) {
                const float* hTp = hT + (par ^ 1) * 160;
                const int tprev = d ? (TT - s) : (s - 1);
                out[(size_t)(eb2 * TT + tprev) * 1024 + d * 512 + n0 + en2] =
                    hTp[en2 * 20 + eb2];
            }
        }
    }

    __syncthreads();
    if (epi) {
        const float* hTp = hT + ((TT - 1) & 1) * 160;
        const int tlast = d ? 0 : (TT - 1);
        out[(size_t)(eb2 * TT + tlast) * 1024 + d * 512 + n0 + en2] =
            hTp[en2 * 20 + eb2];
    }
}

extern "C" void kernel_launch(void* const* d_in, const int* in_sizes, int n_in,
                              void* d_out, int out_size) {
    (void)in_sizes; (void)n_in; (void)out_size;
    const float* x   = (const float*)d_in[0];
    const float* wf  = (const float*)d_in[1];
    const float* bf  = (const float*)d_in[2];
    const float* wb  = (const float*)d_in[3];
    const float* bb  = (const float*)d_in[4];
    const float* h0f = (const float*)d_in[5];
    const float* h0b = (const float*)d_in[6];
    const float* c0f = (const float*)d_in[7];
    const float* c0b = (const float*)d_in[8];
    float* out = (float*)d_out;

    const int psm_bytes = 4 * PTH * 4;  // 40960 (2 stages x (A|B) words)
    cudaFuncSetAttribute(pregemm_kernel, cudaFuncAttributeMaxDynamicSharedMemorySize,
                         psm_bytes);
    const int rsm_bytes = (16 * HPADW + 2 * 8 * 16 * RPAD + 2 * 160) * 4;  // 43520
    cudaFuncSetAttribute(recur_kernel, cudaFuncAttributeMaxDynamicSharedMemorySize,
                         rsm_bytes);

    fill_sentinel_kernel<<<256, 256>>>();
    convert_fp16_kernel<<<512, 256>>>(x, wf, wb);
    dim3 g1(G3 / 128, (TT * BB) / 128, 2);
    pregemm_kernel<<<g1, 256, psm_bytes>>>(bf, bb);
    recur_kernel<<<128, 256, rsm_bytes>>>(wf, wb, h0f, h0b, c0f, c0b, out);
}

// round 17
// speedup vs baseline: 1.6642x; 1.0234x over previous
#include <cuda_runtime.h>
#include <cuda_fp16.h>
#include <cstdint>
#include <cstddef>

#define TT 512
#define BB 16
#define EE 1024
#define HH 512
#define G3 1536
#define SENTH 0x7C01u
#define SENTW 0x7C017C01u

// pre-gate scratch [d][t][col][b] (fp32)
__device__ float g_preg[(size_t)2 * TT * G3 * BB];
// fp16 h staging [d][t][k][b]; sentinel-filled each launch
__device__ unsigned short g_hst16[(size_t)2 * TT * HH * BB];
// fp16 GEMM inputs (written once per launch by init kernel)
__device__ __half g_xh[(size_t)BB * TT * EE];
__device__ __half g_wh[2][(size_t)G3 * EE];

static __device__ __forceinline__ float rcpa(float x) {
    float r; asm("rcp.approx.f32 %0, %1;" : "=f"(r) : "f"(x)); return r;
}
static __device__ __forceinline__ uint32_t packh2(float a, float b) {
    __half2 h = __floats2half2_rn(a, b);
    return *reinterpret_cast<uint32_t*>(&h);
}

// fp16 mma, K=16, fp32 accumulate
static __device__ __forceinline__ void mma16h(float& d0, float& d1, float& d2, float& d3,
                                              uint32_t a0, uint32_t a1, uint32_t a2, uint32_t a3,
                                              uint32_t b0, uint32_t b1) {
    asm volatile(
        "mma.sync.aligned.m16n8k16.row.col.f32.f16.f16.f32 "
        "{%0,%1,%2,%3}, {%4,%5,%6,%7}, {%8,%9}, {%0,%1,%2,%3};"
        : "+f"(d0), "+f"(d1), "+f"(d2), "+f"(d3)
        : "r"(a0), "r"(a1), "r"(a2), "r"(a3), "r"(b0), "r"(b1));
}

// L1-bypassing (gpu-scope) accesses for the handoff
static __device__ __forceinline__ uint4 ld_rlx4u(const void* p) {
    uint4 v;
    asm volatile("ld.relaxed.gpu.global.v4.u32 {%0,%1,%2,%3}, [%4];"
                 : "=r"(v.x), "=r"(v.y), "=r"(v.z), "=r"(v.w) : "l"(p) : "memory");
    return v;
}
static __device__ __forceinline__ void st_rlx16(unsigned short* p, unsigned short v) {
    asm volatile("st.relaxed.gpu.global.u16 [%0], %1;" :: "l"(p), "h"(v) : "memory");
}
static __device__ __forceinline__ bool wsent(uint32_t u) {
    return ((u & 0xFFFFu) == SENTH) | ((u >> 16) == SENTH);
}
static __device__ __forceinline__ bool hass(uint4 v) {
    return wsent(v.x) | wsent(v.y) | wsent(v.z) | wsent(v.w);
}

// fused init: sentinel-fill g_hst16 + convert x/W to fp16 (one launch)
__global__ void init_kernel(const float* __restrict__ x,
                            const float* __restrict__ wf,
                            const float* __restrict__ wb) {
    const size_t stride = (size_t)gridDim.x * blockDim.x;
    const size_t base = blockIdx.x * (size_t)blockDim.x + threadIdx.x;

    const size_t ns4 = (size_t)2 * TT * HH * BB / 8;
    uint4 s = make_uint4(SENTW, SENTW, SENTW, SENTW);
    uint4* hp = reinterpret_cast<uint4*>(g_hst16);
    for (size_t i = base; i < ns4; i += stride) hp[i] = s;

    const size_t nx4 = (size_t)BB * TT * EE / 4;
    for (size_t i = base; i < nx4; i += stride) {
        float4 v = reinterpret_cast<const float4*>(x)[i];
        reinterpret_cast<uint2*>(g_xh)[i] =
            make_uint2(packh2(v.x, v.y), packh2(v.z, v.w));
    }
    const size_t nw4 = (size_t)G3 * EE / 4;
    for (size_t i = base; i < nw4; i += stride) {
        size_t r = i / (EE / 4), cq = i % (EE / 4);
        float4 vf = *reinterpret_cast<const float4*>(wf + r * G3 + cq * 4);
        float4 vb = *reinterpret_cast<const float4*>(wb + r * G3 + cq * 4);
        reinterpret_cast<uint2*>(g_wh[0])[i] =
            make_uint2(packh2(vf.x, vf.y), packh2(vf.z, vf.w));
        reinterpret_cast<uint2*>(g_wh[1])[i] =
            make_uint2(packh2(vb.x, vb.y), packh2(vb.z, vb.w));
    }
}

// ---------------------------------------------------------------------------
// Phase 1: pre-gates = x @ W_x^T + bias — FP16 mma (m16n8k16), fp32 acc.
// M = 8192, N = 1536, K = 1024. CTA tile 128x128x32, 8 warps (2x4), warp
// tile 64x32. cp.async 3-STAGE pipeline (wait_group 1): a full chunk of
// copy latency slack vs the 2-stage version. Rows padded to 20 words.
// ---------------------------------------------------------------------------
#define PTH (128 * 20)  // words per tile

static __device__ __forceinline__ void cp_async16(uint32_t smem_addr, const void* gptr) {
    asm volatile("cp.async.ca.shared.global [%0], [%1], 16;"
                 :: "r"(smem_addr), "l"(gptr) : "memory");
}

__global__ __launch_bounds__(256) void pregemm_kernel(
    const float* __restrict__ bf, const float* __restrict__ bb) {
    extern __shared__ uint32_t psm[];  // [3][ A(128*20) | B(128*20) ] words
    const int d = blockIdx.z;
    const __half* __restrict__ wh   = g_wh[d];
    const float* __restrict__ bias = d ? bb : bf;
    const int row0 = blockIdx.y * 128;
    const int col0 = blockIdx.x * 128;

    const int tid = threadIdx.x;
    const int lane = tid & 31, wid = tid >> 5;
    const int wm = wid >> 2, wn = wid & 3;
    const int g = lane >> 2, t4 = lane & 3;

    float acc[4][4][4];
#pragma unroll
    for (int i = 0; i < 4; i++)
#pragma unroll
        for (int j = 0; j < 4; j++)
#pragma unroll
            for (int r = 0; r < 4; r++) acc[i][j][r] = 0.f;

    auto issue_stage = [&](int st, int k0) {
        uint32_t* As = psm + st * 2 * PTH;
        uint32_t* Bs = As + PTH;
#pragma unroll
        for (int i = 0; i < 2; i++) {
            int idx = tid + i * 256;
            int m = idx >> 2, ch = idx & 3;
            int row = row0 + m;
            int t = row >> 4, b = row & 15;
            cp_async16((uint32_t)__cvta_generic_to_shared(&As[m * 20 + ch * 4]),
                       g_xh + (size_t)(b * TT + t) * EE + k0 + ch * 8);
            cp_async16((uint32_t)__cvta_generic_to_shared(&Bs[m * 20 + ch * 4]),
                       wh + (size_t)(col0 + m) * EE + k0 + ch * 8);
        }
        asm volatile("cp.async.commit_group;" ::: "memory");
    };

    issue_stage(0, 0);
    issue_stage(1, 32);

    int stage = 0;
    for (int kb = 0; kb < 32; kb++) {
        if (kb < 31) {
            asm volatile("cp.async.wait_group 1;" ::: "memory");
        } else {
            asm volatile("cp.async.wait_group 0;" ::: "memory");
        }
        __syncthreads();  // stage kb ready; all mma on buffer (kb+2)%3 done
        if (kb < 30) {
            int st2 = stage + 2; if (st2 >= 3) st2 -= 3;
            issue_stage(st2, (kb + 2) * 32);
        }

        const uint32_t* As = psm + stage * 2 * PTH;
        const uint32_t* Bs = As + PTH;
#pragma unroll
        for (int kt = 0; kt < 2; kt++) {
            int kw = kt * 8;
            uint32_t a[4][4];
#pragma unroll
            for (int mt = 0; mt < 4; mt++) {
                int mb = wm * 64 + mt * 16;
                a[mt][0] = As[(mb + g) * 20 + kw + t4];
                a[mt][1] = As[(mb + g + 8) * 20 + kw + t4];
                a[mt][2] = As[(mb + g) * 20 + kw + 4 + t4];
                a[mt][3] = As[(mb + g + 8) * 20 + kw + 4 + t4];
            }
#pragma unroll
            for (int nt = 0; nt < 4; nt++) {
                int nb = wn * 32 + nt * 8;
                uint32_t b0 = Bs[(nb + g) * 20 + kw + t4];
                uint32_t b1 = Bs[(nb + g) * 20 + kw + 4 + t4];
#pragma unroll
                for (int mt = 0; mt < 4; mt++)
                    mma16h(acc[mt][nt][0], acc[mt][nt][1], acc[mt][nt][2], acc[mt][nt][3],
                           a[mt][0], a[mt][1], a[mt][2], a[mt][3], b0, b1);
            }
        }
        if (++stage == 3) stage = 0;
    }

#pragma unroll
    for (int mt = 0; mt < 4; mt++) {
        int rowb = row0 + wm * 64 + mt * 16 + g;
#pragma unroll
        for (int nt = 0; nt < 4; nt++) {
            int colb = col0 + wn * 32 + nt * 8 + 2 * t4;
#pragma unroll
            for (int r = 0; r < 4; r++) {
                int row = rowb + ((r >= 2) ? 8 : 0);
                int col = colb + (r & 1);
                int t = row >> 4, b = row & 15;
                float v = acc[mt][nt][r] + __ldg(bias + col);
                g_preg[(((size_t)d * TT + t) * G3 + col) * BB + b] = v;
            }
        }
    }
}

// ---------------------------------------------------------------------------
// Phase 2: persistent recurrence — byte-exact R15/R16 (best config, 946us):
// fp16 handoff + fp16 mma, warp-owned 64B hst lines, 16B detect spin +
// one-shot verify, publish-first, parity reduce, deferred coalesced out.
// ---------------------------------------------------------------------------
#define HPADW 260   // hsm row stride in 32-bit words
#define RPAD 25

__global__ __launch_bounds__(256) void recur_kernel(
    const float* __restrict__ wf, const float* __restrict__ wb,
    const float* __restrict__ h0f, const float* __restrict__ h0b,
    const float* __restrict__ c0f, const float* __restrict__ c0b,
    float* __restrict__ out) {
    extern __shared__ float sm[];
    uint32_t* hsm = reinterpret_cast<uint32_t*>(sm);  // 16 x HPADW words
    float* red = sm + 16 * HPADW;                     // 2 x 8 x 16 x RPAD
    float* hT  = red + 2 * 8 * 16 * RPAD;             // 2 x 160

    const int d   = (int)blockIdx.x >> 6;
    const int grp = (int)blockIdx.x & 63;
    const int n0  = grp * 8;
    const float* __restrict__ w  = d ? wb : wf;
    const float* __restrict__ h0 = d ? h0b : h0f;
    const float* __restrict__ c0 = d ? c0b : c0f;
    const float* __restrict__ preg = g_preg + (size_t)d * TT * G3 * BB;
    unsigned short* __restrict__ hst = g_hst16 + (size_t)d * TT * HH * BB;

    const int tid = threadIdx.x, lane = tid & 31, wid = tid >> 5;
    const int g = lane >> 2, t4 = lane & 3;
    const int eb = tid & 15, en = (tid >> 4) & 7;
    const int en2 = tid & 7, eb2 = (tid >> 3) & 15;
    const bool epi = tid < 128;
    const int kbase = wid * 64;
    const int k2 = tid * 2;

    uint32_t breg[4][3][2];
#pragma unroll
    for (int gi = 0; gi < 3; gi++) {
        const float* wr = w + (size_t)(gi * 512 + n0 + g) * G3 + 1024;
#pragma unroll
        for (int kt = 0; kt < 4; kt++) {
            int kk = kbase + kt * 16 + 2 * t4;
            breg[kt][gi][0] = packh2(__ldg(wr + kk), __ldg(wr + kk + 1));
            breg[kt][gi][1] = packh2(__ldg(wr + kk + 8), __ldg(wr + kk + 9));
        }
    }
    float c = epi ? c0[n0 + en] : 0.f;

    {
        uint32_t o = packh2(h0[k2], h0[k2 + 1]);
#pragma unroll
        for (int b = 0; b < 16; b++) hsm[b * HPADW + tid] = o;
    }
    __syncthreads();

    for (int s = 0; s < TT; s++) {
        const int tt = d ? (TT - 1 - s) : s;
        const int par = s & 1;
        float* redp = red + par * (8 * 16 * RPAD);

        float pgi = 0.f, pgj = 0.f, pgo = 0.f;
        if (epi) {
            pgi = __ldg(preg + ((size_t)tt * G3 + (n0 + en)) * BB + eb);
            pgj = __ldg(preg + ((size_t)tt * G3 + (512 + n0 + en)) * BB + eb);
            pgo = __ldg(preg + ((size_t)tt * G3 + (1024 + n0 + en)) * BB + eb);
        }

        if (s > 0) {
            const int tp = d ? (tt + 1) : (tt - 1);
            const unsigned short* sp = hst + ((size_t)tp * HH + k2) * BB;
            uint4 v0, v1, v2, v3;
            do { v0 = ld_rlx4u(sp); } while (hass(v0));
            for (;;) {
                v1 = ld_rlx4u(sp + 8);
                v2 = ld_rlx4u(sp + 16);
                v3 = ld_rlx4u(sp + 24);
                if (!(hass(v1) | hass(v2) | hass(v3))) break;
            }
            const uint32_t* lo0 = &v0.x;
            const uint32_t* lo1 = &v1.x;
            const uint32_t* hi0 = &v2.x;
            const uint32_t* hi1 = &v3.x;
#pragma unroll
            for (int b = 0; b < 16; b++) {
                uint32_t ul = (b < 8) ? lo0[b >> 1] : lo1[(b - 8) >> 1];
                uint32_t uh = (b < 8) ? hi0[b >> 1] : hi1[(b - 8) >> 1];
                uint32_t o = (b & 1) ? __byte_perm(ul, uh, 0x7632)
                                     : __byte_perm(ul, uh, 0x5410);
                hsm[b * HPADW + tid] = o;
            }
        }
        __syncwarp();

        float acc[3][4];
#pragma unroll
        for (int nt = 0; nt < 3; nt++)
#pragma unroll
            for (int r = 0; r < 4; r++) acc[nt][r] = 0.f;

#pragma unroll
        for (int kt = 0; kt < 4; kt++) {
            int kw = (kbase >> 1) + kt * 8;
            uint32_t a0 = hsm[g * HPADW + kw + t4];
            uint32_t a1 = hsm[(g + 8) * HPADW + kw + t4];
            uint32_t a2 = hsm[g * HPADW + kw + 4 + t4];
            uint32_t a3 = hsm[(g + 8) * HPADW + kw + 4 + t4];
#pragma unroll
            for (int nt = 0; nt < 3; nt++)
                mma16h(acc[nt][0], acc[nt][1], acc[nt][2], acc[nt][3],
                       a0, a1, a2, a3, breg[kt][nt][0], breg[kt][nt][1]);
        }

        float* rw = redp + wid * 16 * RPAD;
#pragma unroll
        for (int nt = 0; nt < 3; nt++) {
            int rl = nt * 8 + 2 * t4;
            rw[g * RPAD + rl]           = acc[nt][0];
            rw[g * RPAD + rl + 1]       = acc[nt][1];
            rw[(g + 8) * RPAD + rl]     = acc[nt][2];
            rw[(g + 8) * RPAD + rl + 1] = acc[nt][3];
        }
        __syncthreads();

        if (epi) {
            float si = pgi, sj = pgj, so = pgo;
#pragma unroll
            for (int wq = 0; wq < 8; wq++) {
                const float* rr = redp + (wq * 16 + eb) * RPAD;
                si += rr[en];
                sj += rr[8 + en];
                so += rr[16 + en];
            }
            float ig = rcpa(1.f + __expf(-si));
            float tj = 1.f - 2.f * rcpa(1.f + __expf(2.f * sj));
            c = (1.f - ig) * c + ig * tj;
            float tc = 1.f - 2.f * rcpa(1.f + __expf(2.f * c));
            float h = tc * rcpa(1.f + __expf(-so));

            unsigned short hv = __half_as_ushort(__float2half_rn(h));
            st_rlx16(hst + ((size_t)tt * HH + n0 + en) * BB + eb, hv);
            hT[par * 160 + en * 20 + eb] = h;

            if (s > 0) {
                const float* hTp = hT + (par ^ 1) * 160;
                const int tprev = d ? (TT - s) : (s - 1);
                out[(size_t)(eb2 * TT + tprev) * 1024 + d * 512 + n0 + en2] =
                    hTp[en2 * 20 + eb2];
            }
        }
    }

    __syncthreads();
    if (epi) {
        const float* hTp = hT + ((TT - 1) & 1) * 160;
        const int tlast = d ? 0 : (TT - 1);
        out[(size_t)(eb2 * TT + tlast) * 1024 + d * 512 + n0 + en2] =
            hTp[en2 * 20 + eb2];
    }
}

extern "C" void kernel_launch(void* const* d_in, const int* in_sizes, int n_in,
                              void* d_out, int out_size) {
    (void)in_sizes; (void)n_in; (void)out_size;
    const float* x   = (const float*)d_in[0];
    const float* wf  = (const float*)d_in[1];
    const float* bf  = (const float*)d_in[2];
    const float* wb  = (const float*)d_in[3];
    const float* bb  = (const float*)d_in[4];
    const float* h0f = (const float*)d_in[5];
    const float* h0b = (const float*)d_in[6];
    const float* c0f = (const float*)d_in[7];
    const float* c0b = (const float*)d_in[8];
    float* out = (float*)d_out;

    const int psm_bytes = 3 * 2 * PTH * 4;  // 61440 (3 stages x (A|B) words)
    cudaFuncSetAttribute(pregemm_kernel, cudaFuncAttributeMaxDynamicSharedMemorySize,
                         psm_bytes);
    const int rsm_bytes = (16 * HPADW + 2 * 8 * 16 * RPAD + 2 * 160) * 4;  // 43520
    cudaFuncSetAttribute(recur_kernel, cudaFuncAttributeMaxDynamicSharedMemorySize,
                         rsm_bytes);

    init_kernel<<<512, 256>>>(x, wf, wb);
    dim3 g1(G3 / 128, (TT * BB) / 128, 2);
    pregemm_kernel<<<g1, 256, psm_bytes>>>(bf, bb);
    recur_kernel<<<128, 256, rsm_bytes>>>(wf, wb, h0f, h0b, c0f, c0b, out);
}